// round 13
// baseline (speedup 1.0000x reference)
#include <cuda_runtime.h>
#include <cuda_fp16.h>
#include <cstdint>

// ---------------------------------------------------------------------------
// Problem constants
// ---------------------------------------------------------------------------
#define BATCH 2
#define SEQ   8192
#define DMODEL 1024
#define NHEADS 16
#define HDIM  64
#define WIN   128
#define MROWS (BATCH*SEQ)          // 16384
#define NWIN  (SEQ/WIN)            // 64

// ---------------------------------------------------------------------------
// Scratch (allocation-free rule: __device__ globals) — fp16 pipeline
// ---------------------------------------------------------------------------
__device__ __half g_xh [(size_t)MROWS * DMODEL];
__device__ __half g_qh [(size_t)MROWS * DMODEL];
__device__ __half g_kh [(size_t)MROWS * DMODEL];
__device__ __half g_vh [(size_t)MROWS * DMODEL];
__device__ __half g_ah [(size_t)MROWS * DMODEL];
__device__ __half g_wqh[(size_t)DMODEL * DMODEL];
__device__ __half g_wkh[(size_t)DMODEL * DMODEL];
__device__ __half g_wvh[(size_t)DMODEL * DMODEL];
__device__ __half g_woh[(size_t)DMODEL * DMODEL];

// ---------------------------------------------------------------------------
// Helpers
// ---------------------------------------------------------------------------
__device__ __forceinline__ uint32_t smem_u32(const void* p) {
    uint32_t a;
    asm("{ .reg .u64 t; cvta.to.shared.u64 t, %1; cvt.u32.u64 %0, t; }" : "=r"(a) : "l"(p));
    return a;
}
__device__ __forceinline__ void cp_async16(uint32_t dst, const void* src) {
    asm volatile("cp.async.cg.shared.global [%0], [%1], 16;" :: "r"(dst), "l"(src));
}
#define CP_COMMIT() asm volatile("cp.async.commit_group;" ::: "memory")
#define CP_WAIT1()  asm volatile("cp.async.wait_group 1;" ::: "memory")
#define CP_WAIT0()  asm volatile("cp.async.wait_group 0;" ::: "memory")

// fp16 m16n8k16 mma, fp32 accum (sm_80-era PTX — compiles for plain sm_103)
__device__ __forceinline__ void mma16x8x16(float* c, const uint32_t* a, const uint32_t* b) {
    asm volatile(
        "mma.sync.aligned.m16n8k16.row.col.f32.f16.f16.f32 "
        "{%0,%1,%2,%3}, {%4,%5,%6,%7}, {%8,%9}, {%0,%1,%2,%3};"
        : "+f"(c[0]), "+f"(c[1]), "+f"(c[2]), "+f"(c[3])
        : "r"(a[0]), "r"(a[1]), "r"(a[2]), "r"(a[3]), "r"(b[0]), "r"(b[1]));
}
__device__ __forceinline__ void ldsm_x4(uint32_t* r, uint32_t addr) {
    asm volatile("ldmatrix.sync.aligned.m8n8.x4.shared.b16 {%0,%1,%2,%3}, [%4];"
                 : "=r"(r[0]), "=r"(r[1]), "=r"(r[2]), "=r"(r[3]) : "r"(addr));
}
__device__ __forceinline__ void ldsm_x4t(uint32_t* r, uint32_t addr) {
    asm volatile("ldmatrix.sync.aligned.m8n8.x4.trans.shared.b16 {%0,%1,%2,%3}, [%4];"
                 : "=r"(r[0]), "=r"(r[1]), "=r"(r[2]), "=r"(r[3]) : "r"(addr));
}
__device__ __forceinline__ uint32_t pack_h2(float lo, float hi) {
    __half2 h = __floats2half2_rn(lo, hi);
    return *(uint32_t*)&h;
}

// ---------------------------------------------------------------------------
// fp16 mma GEMM:  C[m,n] = sum_k A[m,k]*B[n,k]    (both half, K-major)
// CTA tile 128x256, 256 threads (8 warps), warp tile 64x64 (MMA:ldsm = 4:1).
// 3-stage cp.async pipeline; per chunk: wait -> barrier -> issue next-next
// load -> compute (race-free: barrier precedes the stage overwrite).
// Smem rows: 64 halfs + 8 pad = 72 halfs = 144B (ldmatrix conflict-free).
// blockIdx.z selects (B, C) pair; half output when Ch* set (QKV), else float.
// ---------------------------------------------------------------------------
#define BM 128
#define BN 256
#define BKH 64
#define KSH 72                              // halfs per smem row
#define TILE_A_HALFS (BM * KSH)             // 9216
#define TILE_B_HALFS (BN * KSH)             // 18432
#define STAGE_BYTES ((TILE_A_HALFS + TILE_B_HALFS) * 2)   // 55296
#define NSTAGE 3
#define GEMM_SMEM_BYTES (NSTAGE * STAGE_BYTES)            // 165888
#define NCH (DMODEL / BKH)                  // 16

__global__ __launch_bounds__(256, 1)
void gemm_f16(const __half* __restrict__ A,
              const __half* __restrict__ B0, const __half* __restrict__ B1,
              const __half* __restrict__ B2,
              float* __restrict__ Cf,
              __half* __restrict__ Ch0, __half* __restrict__ Ch1,
              __half* __restrict__ Ch2)
{
    const __half* B  = (blockIdx.z == 0) ? B0 : (blockIdx.z == 1) ? B1 : B2;
    __half*       Ch = (blockIdx.z == 0) ? Ch0 : (blockIdx.z == 1) ? Ch1 : Ch2;

    extern __shared__ __half smh[];
    const uint32_t smBase = smem_u32(smh);

    const int tid  = threadIdx.x;
    const int wid  = tid >> 5;
    const int lane = tid & 31;
    const int gid  = lane >> 2;
    const int tig  = lane & 3;
    const int moff = (wid & 1) * 64;        // 2 warps in M
    const int noff = (wid >> 1) * 64;       // 4 warps in N
    const int bm   = blockIdx.y * BM;
    const int bn   = blockIdx.x * BN;

    // ldmatrix per-lane base addresses (stage 0, kstep 0)
    uint32_t aAddr[4], bAddr[4];
#pragma unroll
    for (int mi = 0; mi < 4; mi++) {
        const int arow = moff + mi * 16 + (lane & 15);
        aAddr[mi] = smBase + (uint32_t)(arow * KSH) * 2u + ((lane & 16) ? 16u : 0u);
    }
#pragma unroll
    for (int p = 0; p < 4; p++) {
        const int nrow = noff + p * 16 + ((lane >> 4) & 1) * 8 + (lane & 7);
        bAddr[p] = smBase + (uint32_t)(TILE_A_HALFS + nrow * KSH) * 2u +
                   ((lane & 8) ? 16u : 0u);
    }

    float acc[4][8][4];
#pragma unroll
    for (int i = 0; i < 4; i++)
#pragma unroll
        for (int j = 0; j < 8; j++)
#pragma unroll
            for (int r = 0; r < 4; r++) acc[i][j][r] = 0.f;

    auto load_chunk = [&](int ch, int s) {
        const int k0 = ch * BKH;
        const uint32_t aBase = smBase + (uint32_t)s * STAGE_BYTES;
        const uint32_t bBase = aBase + TILE_A_HALFS * 2u;
        // A: 128 rows x 8 chunks = 1024 / 256 thr = 4 each
#pragma unroll
        for (int i = 0; i < 4; i++) {
            const int c   = tid + i * 256;
            const int row = c >> 3;
            const int col = c & 7;
            cp_async16(aBase + row * (KSH * 2) + col * 16,
                       A + (size_t)(bm + row) * DMODEL + k0 + col * 8);
        }
        // B: 256 rows x 8 chunks = 2048 / 256 thr = 8 each
#pragma unroll
        for (int i = 0; i < 8; i++) {
            const int c   = tid + i * 256;
            const int row = c >> 3;
            const int col = c & 7;
            cp_async16(bBase + row * (KSH * 2) + col * 16,
                       B + (size_t)(bn + row) * DMODEL + k0 + col * 8);
        }
        CP_COMMIT();
    };

    load_chunk(0, 0);
    load_chunk(1, 1);

    for (int ch = 0; ch < NCH; ch++) {
        const int s = ch % NSTAGE;
        if (ch + 2 < NCH) CP_WAIT1(); else CP_WAIT0();
        __syncthreads();
        if (ch + 2 < NCH) load_chunk(ch + 2, (ch + 2) % NSTAGE);

        const uint32_t soff = (uint32_t)s * STAGE_BYTES;
#pragma unroll
        for (int ks = 0; ks < 4; ks++) {                 // k16 per step = 32B
            const uint32_t kOff = soff + ks * 32u;
            uint32_t af[4][4], bf[4][4];
#pragma unroll
            for (int mi = 0; mi < 4; mi++) ldsm_x4(af[mi], aAddr[mi] + kOff);
#pragma unroll
            for (int p = 0; p < 4; p++)    ldsm_x4(bf[p],  bAddr[p] + kOff);
#pragma unroll
            for (int mi = 0; mi < 4; mi++)
#pragma unroll
                for (int ni = 0; ni < 8; ni++)
                    mma16x8x16(acc[mi][ni], af[mi], &bf[ni >> 1][(ni & 1) * 2]);
        }
    }
    __syncthreads();

    // epilogue
    if (Ch) {
#pragma unroll
        for (int mi = 0; mi < 4; mi++)
#pragma unroll
            for (int ni = 0; ni < 8; ni++) {
                const int row0 = bm + moff + mi * 16 + gid;
                const int col0 = bn + noff + ni * 8 + 2 * tig;
                __half2* p0 = (__half2*)&Ch[(size_t)row0 * DMODEL + col0];
                __half2* p1 = (__half2*)&Ch[(size_t)(row0 + 8) * DMODEL + col0];
                *p0 = __floats2half2_rn(acc[mi][ni][0], acc[mi][ni][1]);
                *p1 = __floats2half2_rn(acc[mi][ni][2], acc[mi][ni][3]);
            }
    } else {
#pragma unroll
        for (int mi = 0; mi < 4; mi++)
#pragma unroll
            for (int ni = 0; ni < 8; ni++) {
                const int row0 = bm + moff + mi * 16 + gid;
                const int col0 = bn + noff + ni * 8 + 2 * tig;
                *(float2*)&Cf[(size_t)row0 * DMODEL + col0] =
                    make_float2(acc[mi][ni][0], acc[mi][ni][1]);
                *(float2*)&Cf[(size_t)(row0 + 8) * DMODEL + col0] =
                    make_float2(acc[mi][ni][2], acc[mi][ni][3]);
            }
    }
}

// ---------------------------------------------------------------------------
// Merged f32 -> f16 conversion (x + 4 weights in one launch)
// ---------------------------------------------------------------------------
#define XCHUNKS (MROWS * DMODEL / 8)          // 2097152 uint4 chunks
#define WCHUNKS (DMODEL * DMODEL / 8)         // 131072 per weight
#define TOTCHUNKS (XCHUNKS + 4 * WCHUNKS)

__global__ void convert_all_kernel(const float* __restrict__ x,
                                   const float* __restrict__ w0, const float* __restrict__ w1,
                                   const float* __restrict__ w2, const float* __restrict__ w3,
                                   __half* __restrict__ xh,
                                   __half* __restrict__ o0, __half* __restrict__ o1,
                                   __half* __restrict__ o2, __half* __restrict__ o3)
{
    for (int i = blockIdx.x * blockDim.x + threadIdx.x; i < TOTCHUNKS;
         i += gridDim.x * blockDim.x) {
        const float* in;
        __half* out;
        int idx;
        if (i < XCHUNKS) { in = x; out = xh; idx = i; }
        else {
            const int j = i - XCHUNKS;
            const int w = j / WCHUNKS;
            idx = j - w * WCHUNKS;
            in  = (w == 0) ? w0 : (w == 1) ? w1 : (w == 2) ? w2 : w3;
            out = (w == 0) ? o0 : (w == 1) ? o1 : (w == 2) ? o2 : o3;
        }
        float4 v0 = ((const float4*)in)[2 * idx];
        float4 v1 = ((const float4*)in)[2 * idx + 1];
        uint4 o;
        o.x = pack_h2(v0.x, v0.y); o.y = pack_h2(v0.z, v0.w);
        o.z = pack_h2(v1.x, v1.y); o.w = pack_h2(v1.z, v1.w);
        ((uint4*)out)[idx] = o;
    }
}

// ---------------------------------------------------------------------------
// fp16 tensor-core hybrid attention — EXACT R9/R12 version (known good).
// One CTA per (window, head, batch); 8 warps, warp owns 16 query rows.
// 192 keys (64 global + 128 local) in smem. S = Q K^T (m16n8k16), exact
// softmax in registers, P packs directly into fp16 A-frags, O = P V with
// V B-frags via ldmatrix.trans. Smem rows: 64 halfs + 8 pad = 72 halfs.
// ---------------------------------------------------------------------------
#define QS_HALFS (128 * KSH)    // 9216
#define KS_HALFS (192 * KSH)    // 13824
#define VS_HALFS (192 * KSH)
#define ATTN_SMEM_BYTES ((QS_HALFS + KS_HALFS + VS_HALFS) * 2)   // 73728

__global__ __launch_bounds__(256, 1)
void attn_f16(const __half* __restrict__ Q, const __half* __restrict__ K,
              const __half* __restrict__ V, __half* __restrict__ O)
{
    extern __shared__ __half smh[];
    const uint32_t smQ = smem_u32(smh);
    const uint32_t smK = smQ + QS_HALFS * 2u;
    const uint32_t smV = smK + KS_HALFS * 2u;

    const int win  = blockIdx.x;
    const int h    = blockIdx.y;
    const int b    = blockIdx.z;
    const int tid  = threadIdx.x;
    const int wid  = tid >> 5;
    const int lane = tid & 31;
    const int gid  = lane >> 2;   // 0..7
    const int tg   = lane & 3;    // 0..3

    // ---- stage Q (128x64), K (192x64), V (192x64) halfs ----
    const __half* Qg = Q + ((size_t)(b * SEQ + win * WIN)) * DMODEL + h * HDIM;
    for (int i = tid; i < 128 * 8; i += 256) {
        const int row = i >> 3, c8 = i & 7;
        cp_async16(smQ + (uint32_t)(row * KSH) * 2u + c8 * 16,
                   Qg + (size_t)row * DMODEL + c8 * 8);
    }
    for (int i = tid; i < 192 * 8; i += 256) {
        const int row = i >> 3, c8 = i & 7;
        const int tok = (row < 64) ? row : (win * WIN + row - 64);
        const size_t src = ((size_t)(b * SEQ + tok)) * DMODEL + h * HDIM + c8 * 8;
        cp_async16(smK + (uint32_t)(row * KSH) * 2u + c8 * 16, K + src);
        cp_async16(smV + (uint32_t)(row * KSH) * 2u + c8 * 16, V + src);
    }
    CP_COMMIT(); CP_WAIT0();
    __syncthreads();

    // ---- Q A-frags: 4 k16-steps ----
    uint32_t aQ[4][4];
    {
        const uint32_t qb = smQ + (uint32_t)((wid * 16 + (lane & 15)) * KSH) * 2u +
                            ((lane & 16) ? 16u : 0u);
#pragma unroll
        for (int ks = 0; ks < 4; ks++) ldsm_x4(aQ[ks], qb + ks * 32u);
    }

    // ---- S = Q K^T : 24 n8-frags over 192 keys ----
    float sf[24][4];
#pragma unroll
    for (int nf = 0; nf < 24; nf++)
#pragma unroll
        for (int r = 0; r < 4; r++) sf[nf][r] = 0.f;

#pragma unroll
    for (int ks = 0; ks < 4; ks++) {
        uint32_t bf[12][4];
#pragma unroll
        for (int p = 0; p < 12; p++) {
            const int nrow = p * 16 + ((lane >> 4) & 1) * 8 + (lane & 7);
            ldsm_x4(bf[p], smK + (uint32_t)(nrow * KSH) * 2u +
                           ((lane & 8) ? 16u : 0u) + ks * 32u);
        }
#pragma unroll
        for (int p = 0; p < 12; p++) {
            mma16x8x16(sf[2 * p],     aQ[ks], &bf[p][0]);
            mma16x8x16(sf[2 * p + 1], aQ[ks], &bf[p][2]);
        }
    }

    // ---- exact softmax (rows rA = gid, rB = gid+8; scale 1/8 in exp arg) ----
    float mA = -1e30f, mB = -1e30f;
#pragma unroll
    for (int nf = 0; nf < 24; nf++) {
        mA = fmaxf(mA, fmaxf(sf[nf][0], sf[nf][1]));
        mB = fmaxf(mB, fmaxf(sf[nf][2], sf[nf][3]));
    }
    mA = fmaxf(mA, __shfl_xor_sync(0xffffffffu, mA, 1));
    mA = fmaxf(mA, __shfl_xor_sync(0xffffffffu, mA, 2));
    mB = fmaxf(mB, __shfl_xor_sync(0xffffffffu, mB, 1));
    mB = fmaxf(mB, __shfl_xor_sync(0xffffffffu, mB, 2));

    float lA = 0.f, lB = 0.f;
#pragma unroll
    for (int nf = 0; nf < 24; nf++) {
        float p0 = __expf((sf[nf][0] - mA) * 0.125f);
        float p1 = __expf((sf[nf][1] - mA) * 0.125f);
        float p2 = __expf((sf[nf][2] - mB) * 0.125f);
        float p3 = __expf((sf[nf][3] - mB) * 0.125f);
        sf[nf][0] = p0; sf[nf][1] = p1; sf[nf][2] = p2; sf[nf][3] = p3;
        lA += p0 + p1; lB += p2 + p3;
    }
    lA += __shfl_xor_sync(0xffffffffu, lA, 1);
    lA += __shfl_xor_sync(0xffffffffu, lA, 2);
    lB += __shfl_xor_sync(0xffffffffu, lB, 1);
    lB += __shfl_xor_sync(0xffffffffu, lB, 2);

    // ---- O = P V : 12 k16-steps, 8 n8-frags (64 dims) ----
    float oc[8][4];
#pragma unroll
    for (int nf = 0; nf < 8; nf++)
#pragma unroll
        for (int r = 0; r < 4; r++) oc[nf][r] = 0.f;

#pragma unroll
    for (int j = 0; j < 12; j++) {
        // P A-frag for keys 16j..16j+15: identity relayout from C-frags
        uint32_t a[4];
        a[0] = pack_h2(sf[2 * j][0],     sf[2 * j][1]);
        a[1] = pack_h2(sf[2 * j][2],     sf[2 * j][3]);
        a[2] = pack_h2(sf[2 * j + 1][0], sf[2 * j + 1][1]);
        a[3] = pack_h2(sf[2 * j + 1][2], sf[2 * j + 1][3]);

        // V B-frags via ldmatrix.trans: rows = keys, cols = dims
        const uint32_t vb = smV + (uint32_t)((j * 16 + ((lane >> 3) & 1) * 8 + (lane & 7)) * KSH) * 2u +
                            ((lane & 16) ? 16u : 0u);
#pragma unroll
        for (int t = 0; t < 2; t++) {        // dim groups 32t .. 32t+31
            uint32_t bv[4];
            ldsm_x4t(bv, vb + t * 64u);
            mma16x8x16(oc[4 * t],     a, &bv[0]);
            mma16x8x16(oc[4 * t + 1], a, &bv[2]);
            uint32_t bv2[4];
            ldsm_x4t(bv2, vb + t * 64u + 32u);
            mma16x8x16(oc[4 * t + 2], a, &bv2[0]);
            mma16x8x16(oc[4 * t + 3], a, &bv2[2]);
        }
    }

    // ---- epilogue: divide by l, write half ----
    const float invA = 1.f / lA, invB = 1.f / lB;
    const int qrow = win * WIN + wid * 16 + gid;
    __half* outA = O + ((size_t)(b * SEQ + qrow)) * DMODEL + h * HDIM;
    __half* outB = outA + 8 * DMODEL;
#pragma unroll
    for (int nf = 0; nf < 8; nf++) {
        const int col = nf * 8 + 2 * tg;
        *(__half2*)(outA + col) = __floats2half2_rn(oc[nf][0] * invA, oc[nf][1] * invA);
        *(__half2*)(outB + col) = __floats2half2_rn(oc[nf][2] * invB, oc[nf][3] * invB);
    }
}

// ---------------------------------------------------------------------------
extern "C" void kernel_launch(void* const* d_in, const int* in_sizes, int n_in,
                              void* d_out, int out_size)
{
    const float* x  = (const float*)d_in[0];
    const float* Wq = (const float*)d_in[1];
    const float* Wk = (const float*)d_in[2];
    const float* Wv = (const float*)d_in[3];
    const float* Wo = (const float*)d_in[4];
    float* out = (float*)d_out;

    __half *xh, *qh, *kh, *vh, *ah, *wqh, *wkh, *wvh, *woh;
    cudaGetSymbolAddress((void**)&xh,  g_xh);
    cudaGetSymbolAddress((void**)&qh,  g_qh);
    cudaGetSymbolAddress((void**)&kh,  g_kh);
    cudaGetSymbolAddress((void**)&vh,  g_vh);
    cudaGetSymbolAddress((void**)&ah,  g_ah);
    cudaGetSymbolAddress((void**)&wqh, g_wqh);
    cudaGetSymbolAddress((void**)&wkh, g_wkh);
    cudaGetSymbolAddress((void**)&wvh, g_wvh);
    cudaGetSymbolAddress((void**)&woh, g_woh);

    cudaFuncSetAttribute(gemm_f16, cudaFuncAttributeMaxDynamicSharedMemorySize,
                         GEMM_SMEM_BYTES);
    cudaFuncSetAttribute(attn_f16, cudaFuncAttributeMaxDynamicSharedMemorySize,
                         ATTN_SMEM_BYTES);

    // merged f32 -> f16 prep (one launch)
    convert_all_kernel<<<2048, 256>>>(x, Wq, Wk, Wv, Wo, xh, wqh, wkh, wvh, woh);

    // fused QKV projection (half outputs feed attention)
    dim3 gqkv(DMODEL / BN, MROWS / BM, 3);   // (4, 128, 3)
    gemm_f16<<<gqkv, 256, GEMM_SMEM_BYTES>>>(xh, wqh, wkh, wvh,
                                             nullptr, qh, kh, vh);

    dim3 ga(NWIN, NHEADS, BATCH);            // (64, 16, 2)
    attn_f16<<<ga, 256, ATTN_SMEM_BYTES>>>(qh, kh, vh, ah);

    // output projection (float output)
    dim3 go(DMODEL / BN, MROWS / BM, 1);     // (4, 128, 1)
    gemm_f16<<<go, 256, GEMM_SMEM_BYTES>>>(ah, woh, woh, woh,
                                           out, nullptr, nullptr, nullptr);
}

// round 14
// speedup vs baseline: 1.0822x; 1.0822x over previous
#include <cuda_runtime.h>
#include <cuda_fp16.h>
#include <cstdint>

// ---------------------------------------------------------------------------
// Problem constants
// ---------------------------------------------------------------------------
#define BATCH 2
#define SEQ   8192
#define DMODEL 1024
#define NHEADS 16
#define HDIM  64
#define WIN   128
#define MROWS (BATCH*SEQ)          // 16384
#define NWIN  (SEQ/WIN)            // 64

// ---------------------------------------------------------------------------
// Scratch (allocation-free rule: __device__ globals) — fp16 pipeline
// ---------------------------------------------------------------------------
__device__ __half g_xh [(size_t)MROWS * DMODEL];
__device__ __half g_qh [(size_t)MROWS * DMODEL];
__device__ __half g_kh [(size_t)MROWS * DMODEL];
__device__ __half g_vh [(size_t)MROWS * DMODEL];
__device__ __half g_ah [(size_t)MROWS * DMODEL];
__device__ __half g_wqh[(size_t)DMODEL * DMODEL];
__device__ __half g_wkh[(size_t)DMODEL * DMODEL];
__device__ __half g_wvh[(size_t)DMODEL * DMODEL];
__device__ __half g_woh[(size_t)DMODEL * DMODEL];

// ---------------------------------------------------------------------------
// Helpers
// ---------------------------------------------------------------------------
__device__ __forceinline__ uint32_t smem_u32(const void* p) {
    uint32_t a;
    asm("{ .reg .u64 t; cvta.to.shared.u64 t, %1; cvt.u32.u64 %0, t; }" : "=r"(a) : "l"(p));
    return a;
}
__device__ __forceinline__ void cp_async16(uint32_t dst, const void* src) {
    asm volatile("cp.async.cg.shared.global [%0], [%1], 16;" :: "r"(dst), "l"(src));
}
#define CP_COMMIT() asm volatile("cp.async.commit_group;" ::: "memory")
#define CP_WAIT1()  asm volatile("cp.async.wait_group 1;" ::: "memory")
#define CP_WAIT0()  asm volatile("cp.async.wait_group 0;" ::: "memory")

// fp16 m16n8k16 mma, fp32 accum (sm_80-era PTX — compiles for plain sm_103)
__device__ __forceinline__ void mma16x8x16(float* c, const uint32_t* a, const uint32_t* b) {
    asm volatile(
        "mma.sync.aligned.m16n8k16.row.col.f32.f16.f16.f32 "
        "{%0,%1,%2,%3}, {%4,%5,%6,%7}, {%8,%9}, {%0,%1,%2,%3};"
        : "+f"(c[0]), "+f"(c[1]), "+f"(c[2]), "+f"(c[3])
        : "r"(a[0]), "r"(a[1]), "r"(a[2]), "r"(a[3]), "r"(b[0]), "r"(b[1]));
}
__device__ __forceinline__ void ldsm_x4(uint32_t* r, uint32_t addr) {
    asm volatile("ldmatrix.sync.aligned.m8n8.x4.shared.b16 {%0,%1,%2,%3}, [%4];"
                 : "=r"(r[0]), "=r"(r[1]), "=r"(r[2]), "=r"(r[3]) : "r"(addr));
}
__device__ __forceinline__ void ldsm_x4t(uint32_t* r, uint32_t addr) {
    asm volatile("ldmatrix.sync.aligned.m8n8.x4.trans.shared.b16 {%0,%1,%2,%3}, [%4];"
                 : "=r"(r[0]), "=r"(r[1]), "=r"(r[2]), "=r"(r[3]) : "r"(addr));
}
__device__ __forceinline__ uint32_t pack_h2(float lo, float hi) {
    __half2 h = __floats2half2_rn(lo, hi);
    return *(uint32_t*)&h;
}

// ---------------------------------------------------------------------------
// fp16 mma GEMM:  C[m,n] = sum_k A[m,k]*B[n,k]    (both half, K-major)
// CTA tile 128x128, 128 threads (4 warps), warp tile 64x64 (MMA:ldsm = 4:1).
// 3-stage cp.async pipeline; per chunk: wait -> barrier -> issue next-next
// load -> compute (race-free: barrier precedes the stage overwrite).
// ~190 regs x 128 thr -> 2 CTAs/SM; smem 2 x 110.6 KB = 221 KB <= 227 KB.
// Smem rows: 64 halfs + 8 pad = 72 halfs = 144B (ldmatrix conflict-free).
// blockIdx.z selects (B, C) pair; half output when Ch* set (QKV), else float.
// ---------------------------------------------------------------------------
#define BM 128
#define BN 128
#define BKH 64
#define KSH 72                              // halfs per smem row
#define TILE_HALFS (BM * KSH)               // 9216 (A or B tile)
#define STAGE_BYTES (2 * TILE_HALFS * 2)    // A+B one stage = 36864
#define NSTAGE 3
#define GEMM_SMEM_BYTES (NSTAGE * STAGE_BYTES)   // 110592
#define NCH (DMODEL / BKH)                  // 16
#define GTHREADS 128

__global__ __launch_bounds__(GTHREADS, 2)
void gemm_f16(const __half* __restrict__ A,
              const __half* __restrict__ B0, const __half* __restrict__ B1,
              const __half* __restrict__ B2,
              float* __restrict__ Cf,
              __half* __restrict__ Ch0, __half* __restrict__ Ch1,
              __half* __restrict__ Ch2)
{
    const __half* B  = (blockIdx.z == 0) ? B0 : (blockIdx.z == 1) ? B1 : B2;
    __half*       Ch = (blockIdx.z == 0) ? Ch0 : (blockIdx.z == 1) ? Ch1 : Ch2;

    extern __shared__ __half smh[];
    const uint32_t smBase = smem_u32(smh);

    const int tid  = threadIdx.x;
    const int wid  = tid >> 5;              // 0..3
    const int lane = tid & 31;
    const int gid  = lane >> 2;
    const int tig  = lane & 3;
    const int moff = (wid & 1) * 64;        // 2 warps in M
    const int noff = (wid >> 1) * 64;       // 2 warps in N
    const int bm   = blockIdx.y * BM;
    const int bn   = blockIdx.x * BN;

    // ldmatrix per-lane base addresses (stage 0, kstep 0)
    uint32_t aAddr[4], bAddr[4];
#pragma unroll
    for (int mi = 0; mi < 4; mi++) {
        const int arow = moff + mi * 16 + (lane & 15);
        aAddr[mi] = smBase + (uint32_t)(arow * KSH) * 2u + ((lane & 16) ? 16u : 0u);
    }
#pragma unroll
    for (int p = 0; p < 4; p++) {
        const int nrow = noff + p * 16 + ((lane >> 4) & 1) * 8 + (lane & 7);
        bAddr[p] = smBase + (uint32_t)(TILE_HALFS + nrow * KSH) * 2u +
                   ((lane & 8) ? 16u : 0u);
    }

    float acc[4][8][4];
#pragma unroll
    for (int i = 0; i < 4; i++)
#pragma unroll
        for (int j = 0; j < 8; j++)
#pragma unroll
            for (int r = 0; r < 4; r++) acc[i][j][r] = 0.f;

    auto load_chunk = [&](int ch, int s) {
        const int k0 = ch * BKH;
        const uint32_t aBase = smBase + (uint32_t)s * STAGE_BYTES;
        const uint32_t bBase = aBase + TILE_HALFS * 2u;
        // A: 128 rows x 8 chunks = 1024 / 128 thr = 8 each (same for B)
#pragma unroll
        for (int i = 0; i < 8; i++) {
            const int c   = tid + i * GTHREADS;
            const int row = c >> 3;
            const int col = c & 7;
            cp_async16(aBase + row * (KSH * 2) + col * 16,
                       A + (size_t)(bm + row) * DMODEL + k0 + col * 8);
            cp_async16(bBase + row * (KSH * 2) + col * 16,
                       B + (size_t)(bn + row) * DMODEL + k0 + col * 8);
        }
        CP_COMMIT();
    };

    load_chunk(0, 0);
    load_chunk(1, 1);

    for (int ch = 0; ch < NCH; ch++) {
        const int s = ch % NSTAGE;
        if (ch + 2 < NCH) CP_WAIT1(); else CP_WAIT0();
        __syncthreads();
        if (ch + 2 < NCH) load_chunk(ch + 2, (ch + 2) % NSTAGE);

        const uint32_t soff = (uint32_t)s * STAGE_BYTES;
#pragma unroll
        for (int ks = 0; ks < 4; ks++) {                 // k16 per step = 32B
            const uint32_t kOff = soff + ks * 32u;
            uint32_t af[4][4], bf[4][4];
#pragma unroll
            for (int mi = 0; mi < 4; mi++) ldsm_x4(af[mi], aAddr[mi] + kOff);
#pragma unroll
            for (int p = 0; p < 4; p++)    ldsm_x4(bf[p],  bAddr[p] + kOff);
#pragma unroll
            for (int mi = 0; mi < 4; mi++)
#pragma unroll
                for (int ni = 0; ni < 8; ni++)
                    mma16x8x16(acc[mi][ni], af[mi], &bf[ni >> 1][(ni & 1) * 2]);
        }
    }
    __syncthreads();

    // epilogue
    if (Ch) {
#pragma unroll
        for (int mi = 0; mi < 4; mi++)
#pragma unroll
            for (int ni = 0; ni < 8; ni++) {
                const int row0 = bm + moff + mi * 16 + gid;
                const int col0 = bn + noff + ni * 8 + 2 * tig;
                __half2* p0 = (__half2*)&Ch[(size_t)row0 * DMODEL + col0];
                __half2* p1 = (__half2*)&Ch[(size_t)(row0 + 8) * DMODEL + col0];
                *p0 = __floats2half2_rn(acc[mi][ni][0], acc[mi][ni][1]);
                *p1 = __floats2half2_rn(acc[mi][ni][2], acc[mi][ni][3]);
            }
    } else {
#pragma unroll
        for (int mi = 0; mi < 4; mi++)
#pragma unroll
            for (int ni = 0; ni < 8; ni++) {
                const int row0 = bm + moff + mi * 16 + gid;
                const int col0 = bn + noff + ni * 8 + 2 * tig;
                *(float2*)&Cf[(size_t)row0 * DMODEL + col0] =
                    make_float2(acc[mi][ni][0], acc[mi][ni][1]);
                *(float2*)&Cf[(size_t)(row0 + 8) * DMODEL + col0] =
                    make_float2(acc[mi][ni][2], acc[mi][ni][3]);
            }
    }
}

// ---------------------------------------------------------------------------
// Merged f32 -> f16 conversion (x + 4 weights in one launch)
// ---------------------------------------------------------------------------
#define XCHUNKS (MROWS * DMODEL / 8)          // 2097152 uint4 chunks
#define WCHUNKS (DMODEL * DMODEL / 8)         // 131072 per weight
#define TOTCHUNKS (XCHUNKS + 4 * WCHUNKS)

__global__ void convert_all_kernel(const float* __restrict__ x,
                                   const float* __restrict__ w0, const float* __restrict__ w1,
                                   const float* __restrict__ w2, const float* __restrict__ w3,
                                   __half* __restrict__ xh,
                                   __half* __restrict__ o0, __half* __restrict__ o1,
                                   __half* __restrict__ o2, __half* __restrict__ o3)
{
    for (int i = blockIdx.x * blockDim.x + threadIdx.x; i < TOTCHUNKS;
         i += gridDim.x * blockDim.x) {
        const float* in;
        __half* out;
        int idx;
        if (i < XCHUNKS) { in = x; out = xh; idx = i; }
        else {
            const int j = i - XCHUNKS;
            const int w = j / WCHUNKS;
            idx = j - w * WCHUNKS;
            in  = (w == 0) ? w0 : (w == 1) ? w1 : (w == 2) ? w2 : w3;
            out = (w == 0) ? o0 : (w == 1) ? o1 : (w == 2) ? o2 : o3;
        }
        float4 v0 = ((const float4*)in)[2 * idx];
        float4 v1 = ((const float4*)in)[2 * idx + 1];
        uint4 o;
        o.x = pack_h2(v0.x, v0.y); o.y = pack_h2(v0.z, v0.w);
        o.z = pack_h2(v1.x, v1.y); o.w = pack_h2(v1.z, v1.w);
        ((uint4*)out)[idx] = o;
    }
}

// ---------------------------------------------------------------------------
// fp16 tensor-core hybrid attention — EXACT R9/R12 version (known good).
// One CTA per (window, head, batch); 8 warps, warp owns 16 query rows.
// 192 keys (64 global + 128 local) in smem. S = Q K^T (m16n8k16), exact
// softmax in registers, P packs directly into fp16 A-frags, O = P V with
// V B-frags via ldmatrix.trans. Smem rows: 64 halfs + 8 pad = 72 halfs.
// ---------------------------------------------------------------------------
#define QS_HALFS (128 * KSH)    // 9216
#define KS_HALFS (192 * KSH)    // 13824
#define VS_HALFS (192 * KSH)
#define ATTN_SMEM_BYTES ((QS_HALFS + KS_HALFS + VS_HALFS) * 2)   // 73728

__global__ __launch_bounds__(256, 1)
void attn_f16(const __half* __restrict__ Q, const __half* __restrict__ K,
              const __half* __restrict__ V, __half* __restrict__ O)
{
    extern __shared__ __half smh[];
    const uint32_t smQ = smem_u32(smh);
    const uint32_t smK = smQ + QS_HALFS * 2u;
    const uint32_t smV = smK + KS_HALFS * 2u;

    const int win  = blockIdx.x;
    const int h    = blockIdx.y;
    const int b    = blockIdx.z;
    const int tid  = threadIdx.x;
    const int wid  = tid >> 5;
    const int lane = tid & 31;
    const int gid  = lane >> 2;   // 0..7
    const int tg   = lane & 3;    // 0..3

    // ---- stage Q (128x64), K (192x64), V (192x64) halfs ----
    const __half* Qg = Q + ((size_t)(b * SEQ + win * WIN)) * DMODEL + h * HDIM;
    for (int i = tid; i < 128 * 8; i += 256) {
        const int row = i >> 3, c8 = i & 7;
        cp_async16(smQ + (uint32_t)(row * KSH) * 2u + c8 * 16,
                   Qg + (size_t)row * DMODEL + c8 * 8);
    }
    for (int i = tid; i < 192 * 8; i += 256) {
        const int row = i >> 3, c8 = i & 7;
        const int tok = (row < 64) ? row : (win * WIN + row - 64);
        const size_t src = ((size_t)(b * SEQ + tok)) * DMODEL + h * HDIM + c8 * 8;
        cp_async16(smK + (uint32_t)(row * KSH) * 2u + c8 * 16, K + src);
        cp_async16(smV + (uint32_t)(row * KSH) * 2u + c8 * 16, V + src);
    }
    CP_COMMIT(); CP_WAIT0();
    __syncthreads();

    // ---- Q A-frags: 4 k16-steps ----
    uint32_t aQ[4][4];
    {
        const uint32_t qb = smQ + (uint32_t)((wid * 16 + (lane & 15)) * KSH) * 2u +
                            ((lane & 16) ? 16u : 0u);
#pragma unroll
        for (int ks = 0; ks < 4; ks++) ldsm_x4(aQ[ks], qb + ks * 32u);
    }

    // ---- S = Q K^T : 24 n8-frags over 192 keys ----
    float sf[24][4];
#pragma unroll
    for (int nf = 0; nf < 24; nf++)
#pragma unroll
        for (int r = 0; r < 4; r++) sf[nf][r] = 0.f;

#pragma unroll
    for (int ks = 0; ks < 4; ks++) {
        uint32_t bf[12][4];
#pragma unroll
        for (int p = 0; p < 12; p++) {
            const int nrow = p * 16 + ((lane >> 4) & 1) * 8 + (lane & 7);
            ldsm_x4(bf[p], smK + (uint32_t)(nrow * KSH) * 2u +
                           ((lane & 8) ? 16u : 0u) + ks * 32u);
        }
#pragma unroll
        for (int p = 0; p < 12; p++) {
            mma16x8x16(sf[2 * p],     aQ[ks], &bf[p][0]);
            mma16x8x16(sf[2 * p + 1], aQ[ks], &bf[p][2]);
        }
    }

    // ---- exact softmax (rows rA = gid, rB = gid+8; scale 1/8 in exp arg) ----
    float mA = -1e30f, mB = -1e30f;
#pragma unroll
    for (int nf = 0; nf < 24; nf++) {
        mA = fmaxf(mA, fmaxf(sf[nf][0], sf[nf][1]));
        mB = fmaxf(mB, fmaxf(sf[nf][2], sf[nf][3]));
    }
    mA = fmaxf(mA, __shfl_xor_sync(0xffffffffu, mA, 1));
    mA = fmaxf(mA, __shfl_xor_sync(0xffffffffu, mA, 2));
    mB = fmaxf(mB, __shfl_xor_sync(0xffffffffu, mB, 1));
    mB = fmaxf(mB, __shfl_xor_sync(0xffffffffu, mB, 2));

    float lA = 0.f, lB = 0.f;
#pragma unroll
    for (int nf = 0; nf < 24; nf++) {
        float p0 = __expf((sf[nf][0] - mA) * 0.125f);
        float p1 = __expf((sf[nf][1] - mA) * 0.125f);
        float p2 = __expf((sf[nf][2] - mB) * 0.125f);
        float p3 = __expf((sf[nf][3] - mB) * 0.125f);
        sf[nf][0] = p0; sf[nf][1] = p1; sf[nf][2] = p2; sf[nf][3] = p3;
        lA += p0 + p1; lB += p2 + p3;
    }
    lA += __shfl_xor_sync(0xffffffffu, lA, 1);
    lA += __shfl_xor_sync(0xffffffffu, lA, 2);
    lB += __shfl_xor_sync(0xffffffffu, lB, 1);
    lB += __shfl_xor_sync(0xffffffffu, lB, 2);

    // ---- O = P V : 12 k16-steps, 8 n8-frags (64 dims) ----
    float oc[8][4];
#pragma unroll
    for (int nf = 0; nf < 8; nf++)
#pragma unroll
        for (int r = 0; r < 4; r++) oc[nf][r] = 0.f;

#pragma unroll
    for (int j = 0; j < 12; j++) {
        // P A-frag for keys 16j..16j+15: identity relayout from C-frags
        uint32_t a[4];
        a[0] = pack_h2(sf[2 * j][0],     sf[2 * j][1]);
        a[1] = pack_h2(sf[2 * j][2],     sf[2 * j][3]);
        a[2] = pack_h2(sf[2 * j + 1][0], sf[2 * j + 1][1]);
        a[3] = pack_h2(sf[2 * j + 1][2], sf[2 * j + 1][3]);

        // V B-frags via ldmatrix.trans: rows = keys, cols = dims
        const uint32_t vb = smV + (uint32_t)((j * 16 + ((lane >> 3) & 1) * 8 + (lane & 7)) * KSH) * 2u +
                            ((lane & 16) ? 16u : 0u);
#pragma unroll
        for (int t = 0; t < 2; t++) {        // dim groups 32t .. 32t+31
            uint32_t bv[4];
            ldsm_x4t(bv, vb + t * 64u);
            mma16x8x16(oc[4 * t],     a, &bv[0]);
            mma16x8x16(oc[4 * t + 1], a, &bv[2]);
            uint32_t bv2[4];
            ldsm_x4t(bv2, vb + t * 64u + 32u);
            mma16x8x16(oc[4 * t + 2], a, &bv2[0]);
            mma16x8x16(oc[4 * t + 3], a, &bv2[2]);
        }
    }

    // ---- epilogue: divide by l, write half ----
    const float invA = 1.f / lA, invB = 1.f / lB;
    const int qrow = win * WIN + wid * 16 + gid;
    __half* outA = O + ((size_t)(b * SEQ + qrow)) * DMODEL + h * HDIM;
    __half* outB = outA + 8 * DMODEL;
#pragma unroll
    for (int nf = 0; nf < 8; nf++) {
        const int col = nf * 8 + 2 * tg;
        *(__half2*)(outA + col) = __floats2half2_rn(oc[nf][0] * invA, oc[nf][1] * invA);
        *(__half2*)(outB + col) = __floats2half2_rn(oc[nf][2] * invB, oc[nf][3] * invB);
    }
}

// ---------------------------------------------------------------------------
extern "C" void kernel_launch(void* const* d_in, const int* in_sizes, int n_in,
                              void* d_out, int out_size)
{
    const float* x  = (const float*)d_in[0];
    const float* Wq = (const float*)d_in[1];
    const float* Wk = (const float*)d_in[2];
    const float* Wv = (const float*)d_in[3];
    const float* Wo = (const float*)d_in[4];
    float* out = (float*)d_out;

    __half *xh, *qh, *kh, *vh, *ah, *wqh, *wkh, *wvh, *woh;
    cudaGetSymbolAddress((void**)&xh,  g_xh);
    cudaGetSymbolAddress((void**)&qh,  g_qh);
    cudaGetSymbolAddress((void**)&kh,  g_kh);
    cudaGetSymbolAddress((void**)&vh,  g_vh);
    cudaGetSymbolAddress((void**)&ah,  g_ah);
    cudaGetSymbolAddress((void**)&wqh, g_wqh);
    cudaGetSymbolAddress((void**)&wkh, g_wkh);
    cudaGetSymbolAddress((void**)&wvh, g_wvh);
    cudaGetSymbolAddress((void**)&woh, g_woh);

    cudaFuncSetAttribute(gemm_f16, cudaFuncAttributeMaxDynamicSharedMemorySize,
                         GEMM_SMEM_BYTES);
    cudaFuncSetAttribute(attn_f16, cudaFuncAttributeMaxDynamicSharedMemorySize,
                         ATTN_SMEM_BYTES);

    // merged f32 -> f16 prep (one launch)
    convert_all_kernel<<<2048, 256>>>(x, Wq, Wk, Wv, Wo, xh, wqh, wkh, wvh, woh);

    // fused QKV projection (half outputs feed attention)
    dim3 gqkv(DMODEL / BN, MROWS / BM, 3);   // (8, 128, 3)
    gemm_f16<<<gqkv, GTHREADS, GEMM_SMEM_BYTES>>>(xh, wqh, wkh, wvh,
                                                  nullptr, qh, kh, vh);

    dim3 ga(NWIN, NHEADS, BATCH);            // (64, 16, 2)
    attn_f16<<<ga, 256, ATTN_SMEM_BYTES>>>(qh, kh, vh, ah);

    // output projection (float output)
    dim3 go(DMODEL / BN, MROWS / BM, 1);     // (8, 128, 1)
    gemm_f16<<<go, GTHREADS, GEMM_SMEM_BYTES>>>(ah, woh, woh, woh,
                                                out, nullptr, nullptr, nullptr);
}

// round 17
// speedup vs baseline: 1.1615x; 1.0733x over previous
#include <cuda_runtime.h>
#include <cuda_fp16.h>
#include <cstdint>

// ---------------------------------------------------------------------------
// Problem constants
// ---------------------------------------------------------------------------
#define BATCH 2
#define SEQ   8192
#define DMODEL 1024
#define NHEADS 16
#define HDIM  64
#define WIN   128
#define MROWS (BATCH*SEQ)          // 16384
#define NWIN  (SEQ/WIN)            // 64
#define NTILES (NWIN * NHEADS * BATCH)   // 2048
#define NCTA_ATTN 148

// ---------------------------------------------------------------------------
// Scratch (allocation-free rule: __device__ globals) — fp16 pipeline
// ---------------------------------------------------------------------------
__device__ __half g_xh [(size_t)MROWS * DMODEL];
__device__ __half g_qh [(size_t)MROWS * DMODEL];
__device__ __half g_kh [(size_t)MROWS * DMODEL];
__device__ __half g_vh [(size_t)MROWS * DMODEL];
__device__ __half g_ah [(size_t)MROWS * DMODEL];
__device__ __half g_wqh[(size_t)DMODEL * DMODEL];
__device__ __half g_wkh[(size_t)DMODEL * DMODEL];
__device__ __half g_wvh[(size_t)DMODEL * DMODEL];
__device__ __half g_woh[(size_t)DMODEL * DMODEL];

// ---------------------------------------------------------------------------
// Helpers
// ---------------------------------------------------------------------------
__device__ __forceinline__ uint32_t smem_u32(const void* p) {
    uint32_t a;
    asm("{ .reg .u64 t; cvta.to.shared.u64 t, %1; cvt.u32.u64 %0, t; }" : "=r"(a) : "l"(p));
    return a;
}
__device__ __forceinline__ void cp_async16(uint32_t dst, const void* src) {
    asm volatile("cp.async.cg.shared.global [%0], [%1], 16;" :: "r"(dst), "l"(src));
}
#define CP_COMMIT() asm volatile("cp.async.commit_group;" ::: "memory")
#define CP_WAIT1()  asm volatile("cp.async.wait_group 1;" ::: "memory")
#define CP_WAIT0()  asm volatile("cp.async.wait_group 0;" ::: "memory")

// fp16 m16n8k16 mma, fp32 accum (sm_80-era PTX — compiles for plain sm_103)
__device__ __forceinline__ void mma16x8x16(float* c, const uint32_t* a, const uint32_t* b) {
    asm volatile(
        "mma.sync.aligned.m16n8k16.row.col.f32.f16.f16.f32 "
        "{%0,%1,%2,%3}, {%4,%5,%6,%7}, {%8,%9}, {%0,%1,%2,%3};"
        : "+f"(c[0]), "+f"(c[1]), "+f"(c[2]), "+f"(c[3])
        : "r"(a[0]), "r"(a[1]), "r"(a[2]), "r"(a[3]), "r"(b[0]), "r"(b[1]));
}
__device__ __forceinline__ void ldsm_x4(uint32_t* r, uint32_t addr) {
    asm volatile("ldmatrix.sync.aligned.m8n8.x4.shared.b16 {%0,%1,%2,%3}, [%4];"
                 : "=r"(r[0]), "=r"(r[1]), "=r"(r[2]), "=r"(r[3]) : "r"(addr));
}
__device__ __forceinline__ void ldsm_x4t(uint32_t* r, uint32_t addr) {
    asm volatile("ldmatrix.sync.aligned.m8n8.x4.trans.shared.b16 {%0,%1,%2,%3}, [%4];"
                 : "=r"(r[0]), "=r"(r[1]), "=r"(r[2]), "=r"(r[3]) : "r"(addr));
}
__device__ __forceinline__ uint32_t pack_h2(float lo, float hi) {
    __half2 h = __floats2half2_rn(lo, hi);
    return *(uint32_t*)&h;
}

// ---------------------------------------------------------------------------
// fp16 mma GEMM — EXACT R12 configuration (best measured: 55% tensor).
// CTA 128x128, 256 threads (8 warps, warp tile 64x32), 3-stage cp.async.
// ---------------------------------------------------------------------------
#define BM 128
#define BN 128
#define BKH 64
#define KSH 72                            // halfs per smem row
#define TILE_HALFS (128 * KSH)            // 9216
#define STAGE_BYTES (2 * TILE_HALFS * 2)  // A+B one stage = 36864
#define NSTAGE 3
#define GEMM_SMEM_BYTES (NSTAGE * STAGE_BYTES) // 110592
#define NCH (DMODEL / BKH)                // 16

__global__ __launch_bounds__(256, 2)
void gemm_f16(const __half* __restrict__ A,
              const __half* __restrict__ B0, const __half* __restrict__ B1,
              const __half* __restrict__ B2,
              float* __restrict__ Cf,
              __half* __restrict__ Ch0, __half* __restrict__ Ch1,
              __half* __restrict__ Ch2)
{
    const __half* B  = (blockIdx.z == 0) ? B0 : (blockIdx.z == 1) ? B1 : B2;
    __half*       Ch = (blockIdx.z == 0) ? Ch0 : (blockIdx.z == 1) ? Ch1 : Ch2;

    extern __shared__ __half smh[];
    const uint32_t smBase = smem_u32(smh);

    const int tid  = threadIdx.x;
    const int wid  = tid >> 5;
    const int lane = tid & 31;
    const int gid  = lane >> 2;
    const int tig  = lane & 3;
    const int moff = (wid & 1) * 64;
    const int noff = (wid >> 1) * 32;
    const int bm   = blockIdx.y * BM;
    const int bn   = blockIdx.x * BN;

    uint32_t aAddr[4], bAddr[2];
#pragma unroll
    for (int mi = 0; mi < 4; mi++) {
        const int arow = moff + mi * 16 + (lane & 15);
        aAddr[mi] = smBase + (uint32_t)(arow * KSH) * 2u + ((lane & 16) ? 16u : 0u);
    }
#pragma unroll
    for (int p = 0; p < 2; p++) {
        const int nrow = noff + p * 16 + ((lane >> 4) & 1) * 8 + (lane & 7);
        bAddr[p] = smBase + (uint32_t)(TILE_HALFS + nrow * KSH) * 2u + ((lane & 8) ? 16u : 0u);
    }

    float acc[4][4][4];
#pragma unroll
    for (int i = 0; i < 4; i++)
#pragma unroll
        for (int j = 0; j < 4; j++)
#pragma unroll
            for (int r = 0; r < 4; r++) acc[i][j][r] = 0.f;

    auto load_chunk = [&](int ch, int s) {
        const int k0 = ch * BKH;
        const uint32_t aBase = smBase + (uint32_t)s * STAGE_BYTES;
        const uint32_t bBase = aBase + TILE_HALFS * 2u;
#pragma unroll
        for (int i = 0; i < 4; i++) {
            const int c   = tid + i * 256;
            const int row = c >> 3;
            const int col = c & 7;
            cp_async16(aBase + row * (KSH * 2) + col * 16,
                       A + (size_t)(bm + row) * DMODEL + k0 + col * 8);
            cp_async16(bBase + row * (KSH * 2) + col * 16,
                       B + (size_t)(bn + row) * DMODEL + k0 + col * 8);
        }
        CP_COMMIT();
    };

    load_chunk(0, 0);
    load_chunk(1, 1);

    for (int ch = 0; ch < NCH; ch++) {
        const int s = ch % NSTAGE;
        if (ch + 2 < NCH) CP_WAIT1(); else CP_WAIT0();
        __syncthreads();
        if (ch + 2 < NCH) load_chunk(ch + 2, (ch + 2) % NSTAGE);

        const uint32_t soff = (uint32_t)s * STAGE_BYTES;
#pragma unroll
        for (int ks = 0; ks < 4; ks++) {
            const uint32_t kOff = soff + ks * 32u;
            uint32_t af[4][4], bf[2][4];
#pragma unroll
            for (int mi = 0; mi < 4; mi++) ldsm_x4(af[mi], aAddr[mi] + kOff);
#pragma unroll
            for (int p = 0; p < 2; p++)    ldsm_x4(bf[p],  bAddr[p] + kOff);
#pragma unroll
            for (int mi = 0; mi < 4; mi++)
#pragma unroll
                for (int ni = 0; ni < 4; ni++)
                    mma16x8x16(acc[mi][ni], af[mi], &bf[ni >> 1][(ni & 1) * 2]);
        }
    }
    __syncthreads();

    if (Ch) {
#pragma unroll
        for (int mi = 0; mi < 4; mi++)
#pragma unroll
            for (int ni = 0; ni < 4; ni++) {
                const int row0 = bm + moff + mi * 16 + gid;
                const int col0 = bn + noff + ni * 8 + 2 * tig;
                __half2* p0 = (__half2*)&Ch[(size_t)row0 * DMODEL + col0];
                __half2* p1 = (__half2*)&Ch[(size_t)(row0 + 8) * DMODEL + col0];
                *p0 = __floats2half2_rn(acc[mi][ni][0], acc[mi][ni][1]);
                *p1 = __floats2half2_rn(acc[mi][ni][2], acc[mi][ni][3]);
            }
    } else {
#pragma unroll
        for (int mi = 0; mi < 4; mi++)
#pragma unroll
            for (int ni = 0; ni < 4; ni++) {
                const int row0 = bm + moff + mi * 16 + gid;
                const int col0 = bn + noff + ni * 8 + 2 * tig;
                *(float2*)&Cf[(size_t)row0 * DMODEL + col0] =
                    make_float2(acc[mi][ni][0], acc[mi][ni][1]);
                *(float2*)&Cf[(size_t)(row0 + 8) * DMODEL + col0] =
                    make_float2(acc[mi][ni][2], acc[mi][ni][3]);
            }
    }
}

// ---------------------------------------------------------------------------
// Merged f32 -> f16 conversion (x + 4 weights in one launch)
// ---------------------------------------------------------------------------
#define XCHUNKS (MROWS * DMODEL / 8)
#define WCHUNKS (DMODEL * DMODEL / 8)
#define TOTCHUNKS (XCHUNKS + 4 * WCHUNKS)

__global__ void convert_all_kernel(const float* __restrict__ x,
                                   const float* __restrict__ w0, const float* __restrict__ w1,
                                   const float* __restrict__ w2, const float* __restrict__ w3,
                                   __half* __restrict__ xh,
                                   __half* __restrict__ o0, __half* __restrict__ o1,
                                   __half* __restrict__ o2, __half* __restrict__ o3)
{
    for (int i = blockIdx.x * blockDim.x + threadIdx.x; i < TOTCHUNKS;
         i += gridDim.x * blockDim.x) {
        const float* in;
        __half* out;
        int idx;
        if (i < XCHUNKS) { in = x; out = xh; idx = i; }
        else {
            const int j = i - XCHUNKS;
            const int w = j / WCHUNKS;
            idx = j - w * WCHUNKS;
            in  = (w == 0) ? w0 : (w == 1) ? w1 : (w == 2) ? w2 : w3;
            out = (w == 0) ? o0 : (w == 1) ? o1 : (w == 2) ? o2 : o3;
        }
        float4 v0 = ((const float4*)in)[2 * idx];
        float4 v1 = ((const float4*)in)[2 * idx + 1];
        uint4 o;
        o.x = pack_h2(v0.x, v0.y); o.y = pack_h2(v0.z, v0.w);
        o.z = pack_h2(v1.x, v1.y); o.w = pack_h2(v1.z, v1.w);
        ((uint4*)out)[idx] = o;
    }
}

// ---------------------------------------------------------------------------
// Persistent fp16 tensor-core hybrid attention.
// 148 CTAs x 256 threads; each CTA processes tiles t = cta + 148*i (t <
// 2048), double-buffering (Q,K,V) staging so tile i+2's loads overlap tile
// i's compute. Per-tile math is EXACTLY the R12 known-good kernel: S = Q K^T
// (m16n8k16), exact softmax in registers, P -> A-frags (identity), O = P V
// with ldmatrix.trans. Smem: 2 buffers x 72 KB = 144 KB (1 CTA/SM).
// ---------------------------------------------------------------------------
#define QS_HALFS (128 * KSH)    // 9216
#define KS_HALFS (192 * KSH)    // 13824
#define VS_HALFS (192 * KSH)
#define BUF_HALFS (QS_HALFS + KS_HALFS + VS_HALFS)      // 36864
#define BUF_BYTES (BUF_HALFS * 2)                       // 73728
#define ATTN_SMEM_BYTES (2 * BUF_BYTES)                 // 147456

__global__ __launch_bounds__(256, 1)
void attn_f16(const __half* __restrict__ Q, const __half* __restrict__ K,
              const __half* __restrict__ V, __half* __restrict__ O)
{
    extern __shared__ __half smh[];
    const uint32_t smBase = smem_u32(smh);

    const int cta  = blockIdx.x;
    const int tid  = threadIdx.x;
    const int wid  = tid >> 5;
    const int lane = tid & 31;
    const int gid  = lane >> 2;   // 0..7
    const int tg   = lane & 3;    // 0..3

    const int niter = (NTILES - cta + NCTA_ATTN - 1) / NCTA_ATTN;

    // ---- stage one tile's Q (128x64), K (192x64), V (192x64) into buffer s ----
    auto load_tile = [&](int t, int s) {
        const int win = t & (NWIN - 1);
        const int h   = (t >> 6) & (NHEADS - 1);
        const int b   = t >> 10;
        const uint32_t smQ = smBase + (uint32_t)s * BUF_BYTES;
        const uint32_t smK = smQ + QS_HALFS * 2u;
        const uint32_t smV = smK + KS_HALFS * 2u;
        const __half* Qg = Q + ((size_t)(b * SEQ + win * WIN)) * DMODEL + h * HDIM;
        for (int i = tid; i < 128 * 8; i += 256) {
            const int row = i >> 3, c8 = i & 7;
            cp_async16(smQ + (uint32_t)(row * KSH) * 2u + c8 * 16,
                       Qg + (size_t)row * DMODEL + c8 * 8);
        }
        for (int i = tid; i < 192 * 8; i += 256) {
            const int row = i >> 3, c8 = i & 7;
            const int tok = (row < 64) ? row : (win * WIN + row - 64);
            const size_t src = ((size_t)(b * SEQ + tok)) * DMODEL + h * HDIM + c8 * 8;
            cp_async16(smK + (uint32_t)(row * KSH) * 2u + c8 * 16, K + src);
            cp_async16(smV + (uint32_t)(row * KSH) * 2u + c8 * 16, V + src);
        }
        CP_COMMIT();
    };

    if (niter > 0) load_tile(cta, 0);
    if (niter > 1) load_tile(cta + NCTA_ATTN, 1);

    for (int it = 0; it < niter; it++) {
        if (it + 1 < niter) CP_WAIT1(); else CP_WAIT0();
        __syncthreads();

        const int t   = cta + it * NCTA_ATTN;
        const int win = t & (NWIN - 1);
        const int h   = (t >> 6) & (NHEADS - 1);
        const int b   = t >> 10;
        const int s   = it & 1;
        const uint32_t smQ = smBase + (uint32_t)s * BUF_BYTES;
        const uint32_t smK = smQ + QS_HALFS * 2u;
        const uint32_t smV = smK + KS_HALFS * 2u;

        // ---- Q A-frags: 4 k16-steps ----
        uint32_t aQ[4][4];
        {
            const uint32_t qb = smQ + (uint32_t)((wid * 16 + (lane & 15)) * KSH) * 2u +
                                ((lane & 16) ? 16u : 0u);
#pragma unroll
            for (int ks = 0; ks < 4; ks++) ldsm_x4(aQ[ks], qb + ks * 32u);
        }

        // ---- S = Q K^T : 24 n8-frags over 192 keys ----
        float sf[24][4];
#pragma unroll
        for (int nf = 0; nf < 24; nf++)
#pragma unroll
            for (int r = 0; r < 4; r++) sf[nf][r] = 0.f;

#pragma unroll
        for (int ks = 0; ks < 4; ks++) {
            uint32_t bf[12][4];
#pragma unroll
            for (int p = 0; p < 12; p++) {
                const int nrow = p * 16 + ((lane >> 4) & 1) * 8 + (lane & 7);
                ldsm_x4(bf[p], smK + (uint32_t)(nrow * KSH) * 2u +
                               ((lane & 8) ? 16u : 0u) + ks * 32u);
            }
#pragma unroll
            for (int p = 0; p < 12; p++) {
                mma16x8x16(sf[2 * p],     aQ[ks], &bf[p][0]);
                mma16x8x16(sf[2 * p + 1], aQ[ks], &bf[p][2]);
            }
        }

        // ---- exact softmax (rows rA = gid, rB = gid+8; scale 1/8 in exp) ----
        float mA = -1e30f, mB = -1e30f;
#pragma unroll
        for (int nf = 0; nf < 24; nf++) {
            mA = fmaxf(mA, fmaxf(sf[nf][0], sf[nf][1]));
            mB = fmaxf(mB, fmaxf(sf[nf][2], sf[nf][3]));
        }
        mA = fmaxf(mA, __shfl_xor_sync(0xffffffffu, mA, 1));
        mA = fmaxf(mA, __shfl_xor_sync(0xffffffffu, mA, 2));
        mB = fmaxf(mB, __shfl_xor_sync(0xffffffffu, mB, 1));
        mB = fmaxf(mB, __shfl_xor_sync(0xffffffffu, mB, 2));

        float lA = 0.f, lB = 0.f;
#pragma unroll
        for (int nf = 0; nf < 24; nf++) {
            float p0 = __expf((sf[nf][0] - mA) * 0.125f);
            float p1 = __expf((sf[nf][1] - mA) * 0.125f);
            float p2 = __expf((sf[nf][2] - mB) * 0.125f);
            float p3 = __expf((sf[nf][3] - mB) * 0.125f);
            sf[nf][0] = p0; sf[nf][1] = p1; sf[nf][2] = p2; sf[nf][3] = p3;
            lA += p0 + p1; lB += p2 + p3;
        }
        lA += __shfl_xor_sync(0xffffffffu, lA, 1);
        lA += __shfl_xor_sync(0xffffffffu, lA, 2);
        lB += __shfl_xor_sync(0xffffffffu, lB, 1);
        lB += __shfl_xor_sync(0xffffffffu, lB, 2);

        // ---- O = P V : 12 k16-steps, 8 n8-frags (64 dims) ----
        float oc[8][4];
#pragma unroll
        for (int nf = 0; nf < 8; nf++)
#pragma unroll
            for (int r = 0; r < 4; r++) oc[nf][r] = 0.f;

#pragma unroll
        for (int j = 0; j < 12; j++) {
            uint32_t a[4];
            a[0] = pack_h2(sf[2 * j][0],     sf[2 * j][1]);
            a[1] = pack_h2(sf[2 * j][2],     sf[2 * j][3]);
            a[2] = pack_h2(sf[2 * j + 1][0], sf[2 * j + 1][1]);
            a[3] = pack_h2(sf[2 * j + 1][2], sf[2 * j + 1][3]);

            const uint32_t vb = smV +
                (uint32_t)((j * 16 + ((lane >> 3) & 1) * 8 + (lane & 7)) * KSH) * 2u +
                ((lane & 16) ? 16u : 0u);
#pragma unroll
            for (int tgrp = 0; tgrp < 2; tgrp++) {
                uint32_t bv[4];
                ldsm_x4t(bv, vb + tgrp * 64u);
                mma16x8x16(oc[4 * tgrp],     a, &bv[0]);
                mma16x8x16(oc[4 * tgrp + 1], a, &bv[2]);
                uint32_t bv2[4];
                ldsm_x4t(bv2, vb + tgrp * 64u + 32u);
                mma16x8x16(oc[4 * tgrp + 2], a, &bv2[0]);
                mma16x8x16(oc[4 * tgrp + 3], a, &bv2[2]);
            }
        }

        // ---- epilogue: divide by l, write half ----
        const float invA = 1.f / lA, invB = 1.f / lB;
        const int qrow = win * WIN + wid * 16 + gid;
        __half* outA = O + ((size_t)(b * SEQ + qrow)) * DMODEL + h * HDIM;
        __half* outB = outA + 8 * DMODEL;
#pragma unroll
        for (int nf = 0; nf < 8; nf++) {
            const int col = nf * 8 + 2 * tg;
            *(__half2*)(outA + col) = __floats2half2_rn(oc[nf][0] * invA, oc[nf][1] * invA);
            *(__half2*)(outB + col) = __floats2half2_rn(oc[nf][2] * invB, oc[nf][3] * invB);
        }

        // all smem reads of buffer s done -> safe to refill it
        __syncthreads();
        if (it + 2 < niter) load_tile(cta + (it + 2) * NCTA_ATTN, s);
    }
}

// ---------------------------------------------------------------------------
extern "C" void kernel_launch(void* const* d_in, const int* in_sizes, int n_in,
                              void* d_out, int out_size)
{
    const float* x  = (const float*)d_in[0];
    const float* Wq = (const float*)d_in[1];
    const float* Wk = (const float*)d_in[2];
    const float* Wv = (const float*)d_in[3];
    const float* Wo = (const float*)d_in[4];
    float* out = (float*)d_out;

    __half *xh, *qh, *kh, *vh, *ah, *wqh, *wkh, *wvh, *woh;
    cudaGetSymbolAddress((void**)&xh,  g_xh);
    cudaGetSymbolAddress((void**)&qh,  g_qh);
    cudaGetSymbolAddress((void**)&kh,  g_kh);
    cudaGetSymbolAddress((void**)&vh,  g_vh);
    cudaGetSymbolAddress((void**)&ah,  g_ah);
    cudaGetSymbolAddress((void**)&wqh, g_wqh);
    cudaGetSymbolAddress((void**)&wkh, g_wkh);
    cudaGetSymbolAddress((void**)&wvh, g_wvh);
    cudaGetSymbolAddress((void**)&woh, g_woh);

    cudaFuncSetAttribute(gemm_f16, cudaFuncAttributeMaxDynamicSharedMemorySize,
                         GEMM_SMEM_BYTES);
    cudaFuncSetAttribute(attn_f16, cudaFuncAttributeMaxDynamicSharedMemorySize,
                         ATTN_SMEM_BYTES);

    // merged f32 -> f16 prep (one launch)
    convert_all_kernel<<<2048, 256>>>(x, Wq, Wk, Wv, Wo, xh, wqh, wkh, wvh, woh);

    // fused QKV projection (half outputs feed attention)
    dim3 gqkv(DMODEL / BN, MROWS / BM, 3);   // (8, 128, 3)
    gemm_f16<<<gqkv, 256, GEMM_SMEM_BYTES>>>(xh, wqh, wkh, wvh,
                                             nullptr, qh, kh, vh);

    // persistent attention
    attn_f16<<<NCTA_ATTN, 256, ATTN_SMEM_BYTES>>>(qh, kh, vh, ah);

    // output projection (float output)
    dim3 go(DMODEL / BN, MROWS / BM, 1);     // (8, 128, 1)
    gemm_f16<<<go, 256, GEMM_SMEM_BYTES>>>(ah, woh, woh, woh,
                                           out, nullptr, nullptr, nullptr);
}